// round 3
// baseline (speedup 1.0000x reference)
#include <cuda_runtime.h>

// ---------------- problem constants ----------------
#define M_TOK  16384     // BATCH * SEQ
#define DIMN   1024
#define KLR    256
#define BATCHN 4
#define SEQN   4096
#define HEADSN 16
#define DHN    64

// ---------------- scratch (device globals; no allocation allowed) ----------------
// AO overlays g_K: K is dead after the keys projection; attention reads only
// Q/keys/vals and writes AO. Stream ordering guarantees safety.
__device__ float g_Q[16384 * 1024];
__device__ float g_K[16384 * 1024];     // later reused as AO
__device__ float g_V[16384 * 1024];
__device__ float g_keys[4 * 256 * 1024];
__device__ float g_vals[4 * 256 * 1024];

// =====================================================================
// NT SGEMM:  C[m,n] = sum_k A[m*lda+k] * B[n*ldb+k]  (+ bias[n])
// Block tile 128x128, K-tile 8, 256 threads, 8x8 per thread.
// =====================================================================
__global__ __launch_bounds__(256) void sgemm_nt(
    const float* __restrict__ A, const float* __restrict__ B,
    const float* __restrict__ bias, float* __restrict__ C,
    int K, int lda, int ldb, int ldc, int add_bias)
{
    __shared__ float As[8][128 + 4];
    __shared__ float Bs[8][128 + 4];

    const int tid = threadIdx.x;
    const int tx = tid & 15;       // 0..15 -> n microtile
    const int ty = tid >> 4;       // 0..15 -> m microtile
    const int m0 = blockIdx.y * 128;
    const int n0 = blockIdx.x * 128;

    float acc[8][8];
#pragma unroll
    for (int i = 0; i < 8; i++)
#pragma unroll
        for (int j = 0; j < 8; j++) acc[i][j] = 0.f;

    const int arow = tid >> 1;           // 0..127
    const int kcol = (tid & 1) * 4;      // 0 or 4
    const float* Ag = A + (long long)(m0 + arow) * lda + kcol;
    const float* Bg = B + (long long)(n0 + arow) * ldb + kcol;

    for (int k0 = 0; k0 < K; k0 += 8) {
        float4 av = *(const float4*)(Ag + k0);
        float4 bv = *(const float4*)(Bg + k0);
        As[kcol + 0][arow] = av.x; As[kcol + 1][arow] = av.y;
        As[kcol + 2][arow] = av.z; As[kcol + 3][arow] = av.w;
        Bs[kcol + 0][arow] = bv.x; Bs[kcol + 1][arow] = bv.y;
        Bs[kcol + 2][arow] = bv.z; Bs[kcol + 3][arow] = bv.w;
        __syncthreads();
#pragma unroll
        for (int kk = 0; kk < 8; kk++) {
            float4 a0 = *(const float4*)&As[kk][ty * 8];
            float4 a1 = *(const float4*)&As[kk][ty * 8 + 4];
            float4 b0 = *(const float4*)&Bs[kk][tx * 8];
            float4 b1 = *(const float4*)&Bs[kk][tx * 8 + 4];
            float ra[8] = {a0.x, a0.y, a0.z, a0.w, a1.x, a1.y, a1.z, a1.w};
            float rb[8] = {b0.x, b0.y, b0.z, b0.w, b1.x, b1.y, b1.z, b1.w};
#pragma unroll
            for (int i = 0; i < 8; i++)
#pragma unroll
                for (int j = 0; j < 8; j++)
                    acc[i][j] = fmaf(ra[i], rb[j], acc[i][j]);
        }
        __syncthreads();
    }

    float bb[8];
    if (add_bias) {
#pragma unroll
        for (int j = 0; j < 8; j++) bb[j] = bias[n0 + tx * 8 + j];
    } else {
#pragma unroll
        for (int j = 0; j < 8; j++) bb[j] = 0.f;
    }

#pragma unroll
    for (int i = 0; i < 8; i++) {
        long long row = m0 + ty * 8 + i;
        float* Cp = C + row * (long long)ldc + n0 + tx * 8;
        float4 o0, o1;
        o0.x = acc[i][0] + bb[0]; o0.y = acc[i][1] + bb[1];
        o0.z = acc[i][2] + bb[2]; o0.w = acc[i][3] + bb[3];
        o1.x = acc[i][4] + bb[4]; o1.y = acc[i][5] + bb[5];
        o1.z = acc[i][6] + bb[6]; o1.w = acc[i][7] + bb[7];
        *(float4*)Cp = o0;
        *(float4*)(Cp + 4) = o1;
    }
}

// =====================================================================
// TN SGEMM (batched over z):  C[m,n] = sum_p A[p*lda+m] * B[p*ldb+n]
// =====================================================================
__global__ __launch_bounds__(256) void sgemm_tn(
    const float* __restrict__ A, const float* __restrict__ B, float* __restrict__ C,
    int P, int lda, int ldb, int ldc, long long strideB, long long strideC)
{
    B += (long long)blockIdx.z * strideB;
    C += (long long)blockIdx.z * strideC;

    __shared__ float As[8][128 + 4];
    __shared__ float Bs[8][128 + 4];

    const int tid = threadIdx.x;
    const int tx = tid & 15;
    const int ty = tid >> 4;
    const int m0 = blockIdx.y * 128;
    const int n0 = blockIdx.x * 128;

    float acc[8][8];
#pragma unroll
    for (int i = 0; i < 8; i++)
#pragma unroll
        for (int j = 0; j < 8; j++) acc[i][j] = 0.f;

    const int prow = tid >> 5;          // 0..7
    const int mcol = (tid & 31) * 4;    // 0..124

    for (int p0 = 0; p0 < P; p0 += 8) {
        *(float4*)&As[prow][mcol] =
            *(const float4*)(A + (long long)(p0 + prow) * lda + m0 + mcol);
        *(float4*)&Bs[prow][mcol] =
            *(const float4*)(B + (long long)(p0 + prow) * ldb + n0 + mcol);
        __syncthreads();
#pragma unroll
        for (int kk = 0; kk < 8; kk++) {
            float4 a0 = *(const float4*)&As[kk][ty * 8];
            float4 a1 = *(const float4*)&As[kk][ty * 8 + 4];
            float4 b0 = *(const float4*)&Bs[kk][tx * 8];
            float4 b1 = *(const float4*)&Bs[kk][tx * 8 + 4];
            float ra[8] = {a0.x, a0.y, a0.z, a0.w, a1.x, a1.y, a1.z, a1.w};
            float rb[8] = {b0.x, b0.y, b0.z, b0.w, b1.x, b1.y, b1.z, b1.w};
#pragma unroll
            for (int i = 0; i < 8; i++)
#pragma unroll
                for (int j = 0; j < 8; j++)
                    acc[i][j] = fmaf(ra[i], rb[j], acc[i][j]);
        }
        __syncthreads();
    }

#pragma unroll
    for (int i = 0; i < 8; i++) {
        long long row = m0 + ty * 8 + i;
        float* Cp = C + row * (long long)ldc + n0 + tx * 8;
        float4 o0, o1;
        o0.x = acc[i][0]; o0.y = acc[i][1]; o0.z = acc[i][2]; o0.w = acc[i][3];
        o1.x = acc[i][4]; o1.y = acc[i][5]; o1.z = acc[i][6]; o1.w = acc[i][7];
        *(float4*)Cp = o0;
        *(float4*)(Cp + 4) = o1;
    }
}

// =====================================================================
// Fused attention: per (b, h, 64-row q tile). K=256 resident in smem.
// smem: qs[64][64], ks[256][68], vs[256][68], ps[64][256]  = 221184 B
// =====================================================================
#define ATT_SMEM_BYTES (55296 * 4)

__global__ __launch_bounds__(256) void attn_kernel(
    const float* __restrict__ Q, const float* __restrict__ Keys,
    const float* __restrict__ Vals, float* __restrict__ O)
{
    extern __shared__ float sm[];
    float* qs = sm;                    // [64][64]
    float* ks = qs + 64 * 64;          // [256][68]
    float* vs = ks + 256 * 68;         // [256][68]
    float* ps = vs + 256 * 68;         // [64][256]

    const int tid = threadIdx.x;
    const int qt = blockIdx.x;   // q tile (64 rows)
    const int h  = blockIdx.y;
    const int b  = blockIdx.z;

    const long long qbase  = ((long long)b * SEQN + qt * 64) * DIMN + h * DHN;
    const long long kvbase = ((long long)b * KLR) * DIMN + h * DHN;

    // load q tile [64][64]
#pragma unroll
    for (int i = 0; i < 4; i++) {
        int idx = tid + i * 256;
        int r = idx >> 4, c4 = (idx & 15) * 4;
        *(float4*)&qs[r * 64 + c4] =
            *(const float4*)(Q + qbase + (long long)r * DIMN + c4);
    }
    // load keys/vals tiles [256][64] into padded [256][68]
#pragma unroll
    for (int i = 0; i < 16; i++) {
        int idx = tid + i * 256;
        int r = idx >> 4, c4 = (idx & 15) * 4;
        *(float4*)&ks[r * 68 + c4] =
            *(const float4*)(Keys + kvbase + (long long)r * DIMN + c4);
        *(float4*)&vs[r * 68 + c4] =
            *(const float4*)(Vals + kvbase + (long long)r * DIMN + c4);
    }
    __syncthreads();

    // dots: thread owns key column `tid` (0..255)
    float4 kr[16];
#pragma unroll
    for (int d = 0; d < 16; d++) kr[d] = *(const float4*)&ks[tid * 68 + d * 4];

    for (int r = 0; r < 64; r++) {
        float acc = 0.f;
#pragma unroll
        for (int d = 0; d < 16; d++) {
            float4 qv = *(const float4*)&qs[r * 64 + d * 4];
            acc = fmaf(qv.x, kr[d].x, acc);
            acc = fmaf(qv.y, kr[d].y, acc);
            acc = fmaf(qv.z, kr[d].z, acc);
            acc = fmaf(qv.w, kr[d].w, acc);
        }
        ps[r * 256 + tid] = acc * 0.125f;   // * dh^-0.5
    }
    __syncthreads();

    // softmax over 256 per row: warp w handles rows w*8..w*8+7
    const int warp = tid >> 5, lane = tid & 31;
    for (int rr = 0; rr < 8; rr++) {
        int r = warp * 8 + rr;
        float v[8], mx = -1e30f;
#pragma unroll
        for (int j = 0; j < 8; j++) {
            v[j] = ps[r * 256 + lane + j * 32];
            mx = fmaxf(mx, v[j]);
        }
#pragma unroll
        for (int s = 16; s > 0; s >>= 1)
            mx = fmaxf(mx, __shfl_xor_sync(0xffffffffu, mx, s));
        float sum = 0.f;
#pragma unroll
        for (int j = 0; j < 8; j++) { v[j] = __expf(v[j] - mx); sum += v[j]; }
#pragma unroll
        for (int s = 16; s > 0; s >>= 1)
            sum += __shfl_xor_sync(0xffffffffu, sum, s);
        float inv = 1.f / sum;
#pragma unroll
        for (int j = 0; j < 8; j++)
            ps[r * 256 + lane + j * 32] = v[j] * inv;
    }
    __syncthreads();

    // out: thread -> (d = tid%64, 16 rows)
    const int d  = tid & 63;
    const int r0 = (tid >> 6) * 16;
    float acc[16];
#pragma unroll
    for (int i = 0; i < 16; i++) acc[i] = 0.f;
    for (int c = 0; c < 256; c++) {
        float vv = vs[c * 68 + d];
#pragma unroll
        for (int i = 0; i < 16; i++)
            acc[i] = fmaf(ps[(r0 + i) * 256 + c], vv, acc[i]);
    }
#pragma unroll
    for (int i = 0; i < 16; i++)
        O[qbase + (long long)(r0 + i) * DIMN + d] = acc[i];
}

// =====================================================================
// launch
// =====================================================================
extern "C" void kernel_launch(void* const* d_in, const int* in_sizes, int n_in,
                              void* d_out, int out_size)
{
    (void)in_sizes; (void)n_in; (void)out_size;

    const float* x  = (const float*)d_in[0];
    const float* Wq = (const float*)d_in[1];
    const float* Wk = (const float*)d_in[2];
    const float* Wv = (const float*)d_in[3];
    const float* pk = (const float*)d_in[4];
    const float* pv = (const float*)d_in[5];
    const float* Wo = (const float*)d_in[6];
    const float* bo = (const float*)d_in[7];
    float* out = (float*)d_out;

    float *Q, *K, *V, *keys, *vals;
    cudaGetSymbolAddress((void**)&Q, g_Q);
    cudaGetSymbolAddress((void**)&K, g_K);
    cudaGetSymbolAddress((void**)&V, g_V);
    cudaGetSymbolAddress((void**)&keys, g_keys);
    cudaGetSymbolAddress((void**)&vals, g_vals);
    float* AO = K;   // overlay: K is dead after the keys projection

    // 1) Q/K/V projections: [16384,1024] x [1024,1024]^T
    dim3 gbig(DIMN / 128, M_TOK / 128);
    sgemm_nt<<<gbig, 256>>>(x, Wq, nullptr, Q, DIMN, DIMN, DIMN, DIMN, 0);
    sgemm_nt<<<gbig, 256>>>(x, Wk, nullptr, K, DIMN, DIMN, DIMN, DIMN, 0);
    sgemm_nt<<<gbig, 256>>>(x, Wv, nullptr, V, DIMN, DIMN, DIMN, DIMN, 0);

    // 2) low-rank sequence projection per batch
    dim3 gproj(DIMN / 128, KLR / 128, BATCHN);
    sgemm_tn<<<gproj, 256>>>(pk, K, keys, SEQN, KLR, DIMN, DIMN,
                             (long long)SEQN * DIMN, (long long)KLR * DIMN);
    sgemm_tn<<<gproj, 256>>>(pv, V, vals, SEQN, KLR, DIMN, DIMN,
                             (long long)SEQN * DIMN, (long long)KLR * DIMN);

    // 3) fused attention (writes AO over the K buffer)
    cudaFuncSetAttribute(attn_kernel,
                         cudaFuncAttributeMaxDynamicSharedMemorySize,
                         ATT_SMEM_BYTES);
    dim3 gatt(SEQN / 64, HEADSN, BATCHN);
    attn_kernel<<<gatt, 256, ATT_SMEM_BYTES>>>(Q, keys, vals, AO);

    // 4) output projection + bias
    sgemm_nt<<<gbig, 256>>>(AO, Wo, bo, out, DIMN, DIMN, DIMN, DIMN, 1);
}

// round 5
// speedup vs baseline: 2.0986x; 2.0986x over previous
#include <cuda_runtime.h>
#include <cstdint>

// ---------------- problem constants ----------------
#define M_TOK  16384     // BATCH * SEQ
#define DIMN   1024
#define KLR    256
#define BATCHN 4
#define SEQN   4096
#define HEADSN 16
#define DHN    64

// ---------------- scratch (device globals) ----------------
__device__ float g_Q[16384 * 1024];
__device__ float g_K[16384 * 1024];     // later reused as AO
__device__ float g_V[16384 * 1024];
__device__ float g_keys[4 * 256 * 1024];
__device__ float g_vals[4 * 256 * 1024];

// ---------------- tf32 helpers ----------------
__device__ __forceinline__ uint32_t f2tf32(float f) {
    uint32_t u;
    asm("cvt.rna.tf32.f32 %0, %1;" : "=r"(u) : "f"(f));
    return u;
}

__device__ __forceinline__ void mma_tf32(
    float& c0, float& c1, float& c2, float& c3,
    uint32_t a0, uint32_t a1, uint32_t a2, uint32_t a3,
    uint32_t b0, uint32_t b1)
{
    asm volatile(
        "mma.sync.aligned.m16n8k8.row.col.f32.tf32.tf32.f32 "
        "{%0,%1,%2,%3}, {%4,%5,%6,%7}, {%8,%9}, {%0,%1,%2,%3};\n"
        : "+f"(c0), "+f"(c1), "+f"(c2), "+f"(c3)
        : "r"(a0), "r"(a1), "r"(a2), "r"(a3), "r"(b0), "r"(b1));
}

// =====================================================================
// NT TF32 GEMM: C[m,n] = sum_k A[m][k]*B[n][k] (+bias[n])
// Block 128x128, BK=16, 256 threads = 8 warps (2x4), warp tile 64x32.
// smem: [row][k] stride 20 (pad) -> conflict-free fragment LDS.
// =====================================================================
__global__ __launch_bounds__(256) void gemm_nt_tf32(
    const float* __restrict__ A, const float* __restrict__ B,
    const float* __restrict__ bias, float* __restrict__ C,
    int K, int lda, int ldb, int ldc, int add_bias)
{
    __shared__ uint32_t As[128 * 20];
    __shared__ uint32_t Bs[128 * 20];

    const int tid  = threadIdx.x;
    const int wid  = tid >> 5, lane = tid & 31;
    const int g    = lane >> 2, tig = lane & 3;
    const int wm   = wid >> 2;            // 0..1 -> 64 rows
    const int wn   = wid & 3;             // 0..3 -> 32 cols
    const int m0   = blockIdx.y * 128;
    const int n0   = blockIdx.x * 128;

    const int lrow = tid >> 1;            // 0..127
    const int lkg  = (tid & 1) * 8;       // 0 or 8
    const float* Ag = A + (long long)(m0 + lrow) * lda + lkg;
    const float* Bg = B + (long long)(n0 + lrow) * ldb + lkg;

    float acc[4][4][4];
#pragma unroll
    for (int mt = 0; mt < 4; mt++)
#pragma unroll
        for (int nt = 0; nt < 4; nt++)
#pragma unroll
            for (int r = 0; r < 4; r++) acc[mt][nt][r] = 0.f;

    float4 pa0 = *(const float4*)(Ag);
    float4 pa1 = *(const float4*)(Ag + 4);
    float4 pb0 = *(const float4*)(Bg);
    float4 pb1 = *(const float4*)(Bg + 4);

    for (int k0 = 0; k0 < K; k0 += 16) {
        __syncthreads();
        {
            uint4 va0 = make_uint4(f2tf32(pa0.x), f2tf32(pa0.y), f2tf32(pa0.z), f2tf32(pa0.w));
            uint4 va1 = make_uint4(f2tf32(pa1.x), f2tf32(pa1.y), f2tf32(pa1.z), f2tf32(pa1.w));
            uint4 vb0 = make_uint4(f2tf32(pb0.x), f2tf32(pb0.y), f2tf32(pb0.z), f2tf32(pb0.w));
            uint4 vb1 = make_uint4(f2tf32(pb1.x), f2tf32(pb1.y), f2tf32(pb1.z), f2tf32(pb1.w));
            *(uint4*)&As[lrow * 20 + lkg]     = va0;
            *(uint4*)&As[lrow * 20 + lkg + 4] = va1;
            *(uint4*)&Bs[lrow * 20 + lkg]     = vb0;
            *(uint4*)&Bs[lrow * 20 + lkg + 4] = vb1;
        }
        __syncthreads();
        if (k0 + 16 < K) {
            pa0 = *(const float4*)(Ag + k0 + 16);
            pa1 = *(const float4*)(Ag + k0 + 20);
            pb0 = *(const float4*)(Bg + k0 + 16);
            pb1 = *(const float4*)(Bg + k0 + 20);
        }
#pragma unroll
        for (int ks = 0; ks < 2; ks++) {
            uint32_t af[4][4], bf[4][2];
#pragma unroll
            for (int mt = 0; mt < 4; mt++) {
                int mr = wm * 64 + mt * 16 + g;
                af[mt][0] = As[mr * 20 + ks * 8 + tig];
                af[mt][1] = As[(mr + 8) * 20 + ks * 8 + tig];
                af[mt][2] = As[mr * 20 + ks * 8 + tig + 4];
                af[mt][3] = As[(mr + 8) * 20 + ks * 8 + tig + 4];
            }
#pragma unroll
            for (int nt = 0; nt < 4; nt++) {
                int nr = wn * 32 + nt * 8 + g;
                bf[nt][0] = Bs[nr * 20 + ks * 8 + tig];
                bf[nt][1] = Bs[nr * 20 + ks * 8 + tig + 4];
            }
#pragma unroll
            for (int mt = 0; mt < 4; mt++)
#pragma unroll
                for (int nt = 0; nt < 4; nt++)
                    mma_tf32(acc[mt][nt][0], acc[mt][nt][1], acc[mt][nt][2], acc[mt][nt][3],
                             af[mt][0], af[mt][1], af[mt][2], af[mt][3],
                             bf[nt][0], bf[nt][1]);
        }
    }

    // epilogue
#pragma unroll
    for (int nt = 0; nt < 4; nt++) {
        int col = n0 + wn * 32 + nt * 8 + tig * 2;
        float b0 = 0.f, b1 = 0.f;
        if (add_bias) { b0 = bias[col]; b1 = bias[col + 1]; }
#pragma unroll
        for (int mt = 0; mt < 4; mt++) {
            int row = m0 + wm * 64 + mt * 16 + g;
            float2 v0 = make_float2(acc[mt][nt][0] + b0, acc[mt][nt][1] + b1);
            float2 v1 = make_float2(acc[mt][nt][2] + b0, acc[mt][nt][3] + b1);
            *(float2*)(C + (long long)row * ldc + col) = v0;
            *(float2*)(C + (long long)(row + 8) * ldc + col) = v1;
        }
    }
}

// =====================================================================
// TN TF32 GEMM (batched z): C[m,n] = sum_p A[p][m]*B[p][n]
// Block 64x128, BK=16, 256 threads = 8 warps (2x4), warp tile 32x32.
// A tile smem [p][m] stride 72; B tile smem [p][n] stride 136 (conflict-free).
// =====================================================================
__global__ __launch_bounds__(256) void gemm_tn_tf32(
    const float* __restrict__ A, const float* __restrict__ B, float* __restrict__ C,
    int P, int lda, int ldb, int ldc, long long strideB, long long strideC)
{
    B += (long long)blockIdx.z * strideB;
    C += (long long)blockIdx.z * strideC;

    __shared__ uint32_t As[16 * 72];
    __shared__ uint32_t Bs[16 * 136];

    const int tid  = threadIdx.x;
    const int wid  = tid >> 5, lane = tid & 31;
    const int g    = lane >> 2, tig = lane & 3;
    const int wm   = wid >> 2;            // 0..1 -> 32 rows
    const int wn   = wid & 3;             // 0..3 -> 32 cols
    const int m0   = blockIdx.y * 64;
    const int n0   = blockIdx.x * 128;

    const int lp   = tid >> 4;            // 0..15
    const int lma  = (tid & 15) * 4;      // A m offset
    const int lnb  = (tid & 15) * 8;      // B n offset
    const float* Ag = A + (long long)lp * lda + m0 + lma;
    const float* Bg = B + (long long)lp * ldb + n0 + lnb;

    float acc[2][4][4];
#pragma unroll
    for (int mt = 0; mt < 2; mt++)
#pragma unroll
        for (int nt = 0; nt < 4; nt++)
#pragma unroll
            for (int r = 0; r < 4; r++) acc[mt][nt][r] = 0.f;

    float4 pa  = *(const float4*)(Ag);
    float4 pb0 = *(const float4*)(Bg);
    float4 pb1 = *(const float4*)(Bg + 4);

    for (int p0 = 0; p0 < P; p0 += 16) {
        __syncthreads();
        {
            uint4 va  = make_uint4(f2tf32(pa.x),  f2tf32(pa.y),  f2tf32(pa.z),  f2tf32(pa.w));
            uint4 vb0 = make_uint4(f2tf32(pb0.x), f2tf32(pb0.y), f2tf32(pb0.z), f2tf32(pb0.w));
            uint4 vb1 = make_uint4(f2tf32(pb1.x), f2tf32(pb1.y), f2tf32(pb1.z), f2tf32(pb1.w));
            *(uint4*)&As[lp * 72 + lma]      = va;
            *(uint4*)&Bs[lp * 136 + lnb]     = vb0;
            *(uint4*)&Bs[lp * 136 + lnb + 4] = vb1;
        }
        __syncthreads();
        if (p0 + 16 < P) {
            pa  = *(const float4*)(Ag + (long long)(p0 + 16) * lda);
            pb0 = *(const float4*)(Bg + (long long)(p0 + 16) * ldb);
            pb1 = *(const float4*)(Bg + (long long)(p0 + 16) * ldb + 4);
        }
#pragma unroll
        for (int ks = 0; ks < 2; ks++) {
            uint32_t af[2][4], bf[4][2];
#pragma unroll
            for (int mt = 0; mt < 2; mt++) {
                int bm = wm * 32 + mt * 16 + g;
                af[mt][0] = As[(ks * 8 + tig) * 72 + bm];
                af[mt][1] = As[(ks * 8 + tig) * 72 + bm + 8];
                af[mt][2] = As[(ks * 8 + tig + 4) * 72 + bm];
                af[mt][3] = As[(ks * 8 + tig + 4) * 72 + bm + 8];
            }
#pragma unroll
            for (int nt = 0; nt < 4; nt++) {
                int bn = wn * 32 + nt * 8 + g;
                bf[nt][0] = Bs[(ks * 8 + tig) * 136 + bn];
                bf[nt][1] = Bs[(ks * 8 + tig + 4) * 136 + bn];
            }
#pragma unroll
            for (int mt = 0; mt < 2; mt++)
#pragma unroll
                for (int nt = 0; nt < 4; nt++)
                    mma_tf32(acc[mt][nt][0], acc[mt][nt][1], acc[mt][nt][2], acc[mt][nt][3],
                             af[mt][0], af[mt][1], af[mt][2], af[mt][3],
                             bf[nt][0], bf[nt][1]);
        }
    }

#pragma unroll
    for (int mt = 0; mt < 2; mt++) {
        int row = m0 + wm * 32 + mt * 16 + g;
#pragma unroll
        for (int nt = 0; nt < 4; nt++) {
            int col = n0 + wn * 32 + nt * 8 + tig * 2;
            *(float2*)(C + (long long)row * ldc + col) =
                make_float2(acc[mt][nt][0], acc[mt][nt][1]);
            *(float2*)(C + (long long)(row + 8) * ldc + col) =
                make_float2(acc[mt][nt][2], acc[mt][nt][3]);
        }
    }
}

// =====================================================================
// Fused attention: per (b, h, 64-row q tile). K=256 resident in smem.
// =====================================================================
#define ATT_SMEM_BYTES (55296 * 4)

__global__ __launch_bounds__(256) void attn_kernel(
    const float* __restrict__ Q, const float* __restrict__ Keys,
    const float* __restrict__ Vals, float* __restrict__ O)
{
    extern __shared__ float sm[];
    float* qs = sm;                    // [64][64]
    float* ks = qs + 64 * 64;          // [256][68]
    float* vs = ks + 256 * 68;         // [256][68]
    float* ps = vs + 256 * 68;         // [64][256]

    const int tid = threadIdx.x;
    const int qt = blockIdx.x;
    const int h  = blockIdx.y;
    const int b  = blockIdx.z;

    const long long qbase  = ((long long)b * SEQN + qt * 64) * DIMN + h * DHN;
    const long long kvbase = ((long long)b * KLR) * DIMN + h * DHN;

#pragma unroll
    for (int i = 0; i < 4; i++) {
        int idx = tid + i * 256;
        int r = idx >> 4, c4 = (idx & 15) * 4;
        *(float4*)&qs[r * 64 + c4] =
            *(const float4*)(Q + qbase + (long long)r * DIMN + c4);
    }
#pragma unroll
    for (int i = 0; i < 16; i++) {
        int idx = tid + i * 256;
        int r = idx >> 4, c4 = (idx & 15) * 4;
        *(float4*)&ks[r * 68 + c4] =
            *(const float4*)(Keys + kvbase + (long long)r * DIMN + c4);
        *(float4*)&vs[r * 68 + c4] =
            *(const float4*)(Vals + kvbase + (long long)r * DIMN + c4);
    }
    __syncthreads();

    float4 kr[16];
#pragma unroll
    for (int d = 0; d < 16; d++) kr[d] = *(const float4*)&ks[tid * 68 + d * 4];

    for (int r = 0; r < 64; r++) {
        float acc = 0.f;
#pragma unroll
        for (int d = 0; d < 16; d++) {
            float4 qv = *(const float4*)&qs[r * 64 + d * 4];
            acc = fmaf(qv.x, kr[d].x, acc);
            acc = fmaf(qv.y, kr[d].y, acc);
            acc = fmaf(qv.z, kr[d].z, acc);
            acc = fmaf(qv.w, kr[d].w, acc);
        }
        ps[r * 256 + tid] = acc * 0.125f;
    }
    __syncthreads();

    const int warp = tid >> 5, lane = tid & 31;
    for (int rr = 0; rr < 8; rr++) {
        int r = warp * 8 + rr;
        float v[8], mx = -1e30f;
#pragma unroll
        for (int j = 0; j < 8; j++) {
            v[j] = ps[r * 256 + lane + j * 32];
            mx = fmaxf(mx, v[j]);
        }
#pragma unroll
        for (int s = 16; s > 0; s >>= 1)
            mx = fmaxf(mx, __shfl_xor_sync(0xffffffffu, mx, s));
        float sum = 0.f;
#pragma unroll
        for (int j = 0; j < 8; j++) { v[j] = __expf(v[j] - mx); sum += v[j]; }
#pragma unroll
        for (int s = 16; s > 0; s >>= 1)
            sum += __shfl_xor_sync(0xffffffffu, sum, s);
        float inv = 1.f / sum;
#pragma unroll
        for (int j = 0; j < 8; j++)
            ps[r * 256 + lane + j * 32] = v[j] * inv;
    }
    __syncthreads();

    const int d  = tid & 63;
    const int r0 = (tid >> 6) * 16;
    float acc[16];
#pragma unroll
    for (int i = 0; i < 16; i++) acc[i] = 0.f;
    for (int c = 0; c < 256; c++) {
        float vv = vs[c * 68 + d];
#pragma unroll
        for (int i = 0; i < 16; i++)
            acc[i] = fmaf(ps[(r0 + i) * 256 + c], vv, acc[i]);
    }
#pragma unroll
    for (int i = 0; i < 16; i++)
        O[qbase + (long long)(r0 + i) * DIMN + d] = acc[i];
}

// =====================================================================
// launch
// =====================================================================
extern "C" void kernel_launch(void* const* d_in, const int* in_sizes, int n_in,
                              void* d_out, int out_size)
{
    (void)in_sizes; (void)n_in; (void)out_size;

    const float* x  = (const float*)d_in[0];
    const float* Wq = (const float*)d_in[1];
    const float* Wk = (const float*)d_in[2];
    const float* Wv = (const float*)d_in[3];
    const float* pk = (const float*)d_in[4];
    const float* pv = (const float*)d_in[5];
    const float* Wo = (const float*)d_in[6];
    const float* bo = (const float*)d_in[7];
    float* out = (float*)d_out;

    float *Q, *K, *V, *keys, *vals;
    cudaGetSymbolAddress((void**)&Q, g_Q);
    cudaGetSymbolAddress((void**)&K, g_K);
    cudaGetSymbolAddress((void**)&V, g_V);
    cudaGetSymbolAddress((void**)&keys, g_keys);
    cudaGetSymbolAddress((void**)&vals, g_vals);
    float* AO = K;   // overlay: K is dead after the keys projection

    // 1) Q/K/V projections (TF32 tensor cores)
    dim3 gbig(DIMN / 128, M_TOK / 128);
    gemm_nt_tf32<<<gbig, 256>>>(x, Wq, nullptr, Q, DIMN, DIMN, DIMN, DIMN, 0);
    gemm_nt_tf32<<<gbig, 256>>>(x, Wk, nullptr, K, DIMN, DIMN, DIMN, DIMN, 0);
    gemm_nt_tf32<<<gbig, 256>>>(x, Wv, nullptr, V, DIMN, DIMN, DIMN, DIMN, 0);

    // 2) low-rank sequence projection per batch (TF32)
    dim3 gproj(DIMN / 128, KLR / 64, BATCHN);
    gemm_tn_tf32<<<gproj, 256>>>(pk, K, keys, SEQN, KLR, DIMN, DIMN,
                                 (long long)SEQN * DIMN, (long long)KLR * DIMN);
    gemm_tn_tf32<<<gproj, 256>>>(pv, V, vals, SEQN, KLR, DIMN, DIMN,
                                 (long long)SEQN * DIMN, (long long)KLR * DIMN);

    // 3) fused attention (writes AO over the K buffer)
    cudaFuncSetAttribute(attn_kernel,
                         cudaFuncAttributeMaxDynamicSharedMemorySize,
                         ATT_SMEM_BYTES);
    dim3 gatt(SEQN / 64, HEADSN, BATCHN);
    attn_kernel<<<gatt, 256, ATT_SMEM_BYTES>>>(Q, keys, vals, AO);

    // 4) output projection + bias (TF32)
    gemm_nt_tf32<<<gbig, 256>>>(AO, Wo, bo, out, DIMN, DIMN, DIMN, DIMN, 1);
}

// round 6
// speedup vs baseline: 2.2310x; 1.0631x over previous
#include <cuda_runtime.h>
#include <cstdint>

// ---------------- problem constants ----------------
#define M_TOK  16384     // BATCH * SEQ
#define DIMN   1024
#define KLR    256
#define BATCHN 4
#define SEQN   4096
#define HEADSN 16
#define DHN    64

// ---------------- scratch (device globals) ----------------
__device__ float g_Q[16384 * 1024];
__device__ float g_K[16384 * 1024];     // later reused as AO
__device__ float g_V[16384 * 1024];
__device__ float g_keys[4 * 256 * 1024];
__device__ float g_vals[4 * 256 * 1024];
// tf32-rounded copies of inputs
__device__ float g_xt[16384 * 1024];
__device__ float g_wqt[1024 * 1024];
__device__ float g_wkt[1024 * 1024];
__device__ float g_wvt[1024 * 1024];
__device__ float g_wot[1024 * 1024];
__device__ float g_pkt[4096 * 256];
__device__ float g_pvt[4096 * 256];

// ---------------- tf32 helpers ----------------
__device__ __forceinline__ float tf32r(float f) {
    uint32_t u;
    asm("cvt.rna.tf32.f32 %0, %1;" : "=r"(u) : "f"(f));
    return __uint_as_float(u);
}

__device__ __forceinline__ void mma_tf32(
    float& c0, float& c1, float& c2, float& c3,
    uint32_t a0, uint32_t a1, uint32_t a2, uint32_t a3,
    uint32_t b0, uint32_t b1)
{
    asm volatile(
        "mma.sync.aligned.m16n8k8.row.col.f32.tf32.tf32.f32 "
        "{%0,%1,%2,%3}, {%4,%5,%6,%7}, {%8,%9}, {%0,%1,%2,%3};\n"
        : "+f"(c0), "+f"(c1), "+f"(c2), "+f"(c3)
        : "r"(a0), "r"(a1), "r"(a2), "r"(a3), "r"(b0), "r"(b1));
}

__device__ __forceinline__ void cp16(uint32_t smem, const void* g) {
    asm volatile("cp.async.cg.shared.global [%0], [%1], 16;\n"
                 :: "r"(smem), "l"(g));
}
__device__ __forceinline__ void cp_commit() {
    asm volatile("cp.async.commit_group;\n");
}
__device__ __forceinline__ void cp_wait0() {
    asm volatile("cp.async.wait_group 0;\n");
}

// ---------------- prep: round to tf32 (RNA) ----------------
__global__ __launch_bounds__(256) void round_tf32_kernel(
    const float* __restrict__ in, float* __restrict__ out, int n4)
{
    int i = blockIdx.x * 256 + threadIdx.x;
    if (i < n4) {
        float4 v = ((const float4*)in)[i];
        v.x = tf32r(v.x); v.y = tf32r(v.y); v.z = tf32r(v.z); v.w = tf32r(v.w);
        ((float4*)out)[i] = v;
    }
}

// =====================================================================
// NT TF32 GEMM (pipelined): C[m,n] = sum_k A[m][k]*B[n][k] (+bias)
// Inputs pre-rounded to tf32. Block 128x128, BK=16, 256 thr, 8 warps.
// Double-buffered smem + cp.async; one __syncthreads per K-tile.
// round_out: round C to tf32 (for K/V feeding the TN GEMM).
// =====================================================================
__global__ __launch_bounds__(256, 2) void gemm_nt_tf32(
    const float* __restrict__ A, const float* __restrict__ B,
    const float* __restrict__ bias, float* __restrict__ C,
    int K, int lda, int ldb, int ldc, int add_bias, int round_out)
{
    __shared__ uint32_t As[2][128 * 20];
    __shared__ uint32_t Bs[2][128 * 20];

    const int tid  = threadIdx.x;
    const int wid  = tid >> 5, lane = tid & 31;
    const int g    = lane >> 2, tig = lane & 3;
    const int wm   = wid >> 2;            // 0..1 -> 64 rows
    const int wn   = wid & 3;             // 0..3 -> 32 cols
    const int m0   = blockIdx.y * 128;
    const int n0   = blockIdx.x * 128;

    const int lrow = tid >> 1;            // 0..127
    const int lkg  = (tid & 1) * 8;       // 0 or 8
    const float* Ag = A + (long long)(m0 + lrow) * lda + lkg;
    const float* Bg = B + (long long)(n0 + lrow) * ldb + lkg;

    const uint32_t sa0 = (uint32_t)__cvta_generic_to_shared(&As[0][lrow * 20 + lkg]);
    const uint32_t sa1 = (uint32_t)__cvta_generic_to_shared(&As[1][lrow * 20 + lkg]);
    const uint32_t sb0 = (uint32_t)__cvta_generic_to_shared(&Bs[0][lrow * 20 + lkg]);
    const uint32_t sb1 = (uint32_t)__cvta_generic_to_shared(&Bs[1][lrow * 20 + lkg]);

    float acc[4][4][4];
#pragma unroll
    for (int mt = 0; mt < 4; mt++)
#pragma unroll
        for (int nt = 0; nt < 4; nt++)
#pragma unroll
            for (int r = 0; r < 4; r++) acc[mt][nt][r] = 0.f;

    // prologue: stage k0=0 into buf 0
    cp16(sa0, Ag);      cp16(sa0 + 16, Ag + 4);
    cp16(sb0, Bg);      cp16(sb0 + 16, Bg + 4);
    cp_commit();

    int buf = 0;
    for (int k0 = 0; k0 < K; k0 += 16) {
        cp_wait0();
        __syncthreads();
        if (k0 + 16 < K) {
            uint32_t da = buf ? sa0 : sa1;
            uint32_t db = buf ? sb0 : sb1;
            cp16(da, Ag + k0 + 16);      cp16(da + 16, Ag + k0 + 20);
            cp16(db, Bg + k0 + 16);      cp16(db + 16, Bg + k0 + 20);
            cp_commit();
        }
        const uint32_t* Ab = As[buf];
        const uint32_t* Bb = Bs[buf];
#pragma unroll
        for (int ks = 0; ks < 2; ks++) {
            uint32_t af[4][4], bf[4][2];
#pragma unroll
            for (int mt = 0; mt < 4; mt++) {
                int mr = wm * 64 + mt * 16 + g;
                af[mt][0] = Ab[mr * 20 + ks * 8 + tig];
                af[mt][1] = Ab[(mr + 8) * 20 + ks * 8 + tig];
                af[mt][2] = Ab[mr * 20 + ks * 8 + tig + 4];
                af[mt][3] = Ab[(mr + 8) * 20 + ks * 8 + tig + 4];
            }
#pragma unroll
            for (int nt = 0; nt < 4; nt++) {
                int nr = wn * 32 + nt * 8 + g;
                bf[nt][0] = Bb[nr * 20 + ks * 8 + tig];
                bf[nt][1] = Bb[nr * 20 + ks * 8 + tig + 4];
            }
#pragma unroll
            for (int mt = 0; mt < 4; mt++)
#pragma unroll
                for (int nt = 0; nt < 4; nt++)
                    mma_tf32(acc[mt][nt][0], acc[mt][nt][1], acc[mt][nt][2], acc[mt][nt][3],
                             af[mt][0], af[mt][1], af[mt][2], af[mt][3],
                             bf[nt][0], bf[nt][1]);
        }
        buf ^= 1;
    }

    // epilogue
#pragma unroll
    for (int nt = 0; nt < 4; nt++) {
        int col = n0 + wn * 32 + nt * 8 + tig * 2;
        float b0 = 0.f, b1 = 0.f;
        if (add_bias) { b0 = bias[col]; b1 = bias[col + 1]; }
#pragma unroll
        for (int mt = 0; mt < 4; mt++) {
            int row = m0 + wm * 64 + mt * 16 + g;
            float v00 = acc[mt][nt][0] + b0, v01 = acc[mt][nt][1] + b1;
            float v10 = acc[mt][nt][2] + b0, v11 = acc[mt][nt][3] + b1;
            if (round_out) {
                v00 = tf32r(v00); v01 = tf32r(v01);
                v10 = tf32r(v10); v11 = tf32r(v11);
            }
            *(float2*)(C + (long long)row * ldc + col) = make_float2(v00, v01);
            *(float2*)(C + (long long)(row + 8) * ldc + col) = make_float2(v10, v11);
        }
    }
}

// =====================================================================
// TN TF32 GEMM (batched z, pipelined): C[m,n] = sum_p A[p][m]*B[p][n]
// Inputs pre-rounded. Block 64x128, BK=16, 256 thr, warp tile 32x32.
// =====================================================================
__global__ __launch_bounds__(256) void gemm_tn_tf32(
    const float* __restrict__ A, const float* __restrict__ B, float* __restrict__ C,
    int P, int lda, int ldb, int ldc, long long strideB, long long strideC)
{
    B += (long long)blockIdx.z * strideB;
    C += (long long)blockIdx.z * strideC;

    __shared__ uint32_t As[2][16 * 72];
    __shared__ uint32_t Bs[2][16 * 136];

    const int tid  = threadIdx.x;
    const int wid  = tid >> 5, lane = tid & 31;
    const int g    = lane >> 2, tig = lane & 3;
    const int wm   = wid >> 2;            // 0..1 -> 32 rows
    const int wn   = wid & 3;             // 0..3 -> 32 cols
    const int m0   = blockIdx.y * 64;
    const int n0   = blockIdx.x * 128;

    const int lp   = tid >> 4;            // 0..15
    const int lma  = (tid & 15) * 4;
    const int lnb  = (tid & 15) * 8;
    const float* Ag = A + (long long)lp * lda + m0 + lma;
    const float* Bg = B + (long long)lp * ldb + n0 + lnb;

    const uint32_t sa0 = (uint32_t)__cvta_generic_to_shared(&As[0][lp * 72 + lma]);
    const uint32_t sa1 = (uint32_t)__cvta_generic_to_shared(&As[1][lp * 72 + lma]);
    const uint32_t sb0 = (uint32_t)__cvta_generic_to_shared(&Bs[0][lp * 136 + lnb]);
    const uint32_t sb1 = (uint32_t)__cvta_generic_to_shared(&Bs[1][lp * 136 + lnb]);

    float acc[2][4][4];
#pragma unroll
    for (int mt = 0; mt < 2; mt++)
#pragma unroll
        for (int nt = 0; nt < 4; nt++)
#pragma unroll
            for (int r = 0; r < 4; r++) acc[mt][nt][r] = 0.f;

    cp16(sa0, Ag);
    cp16(sb0, Bg);   cp16(sb0 + 16, Bg + 4);
    cp_commit();

    int buf = 0;
    for (int p0 = 0; p0 < P; p0 += 16) {
        cp_wait0();
        __syncthreads();
        if (p0 + 16 < P) {
            uint32_t da = buf ? sa0 : sa1;
            uint32_t db = buf ? sb0 : sb1;
            const float* An = Ag + (long long)(p0 + 16) * lda;
            const float* Bn = Bg + (long long)(p0 + 16) * ldb;
            cp16(da, An);
            cp16(db, Bn);   cp16(db + 16, Bn + 4);
            cp_commit();
        }
        const uint32_t* Ab = As[buf];
        const uint32_t* Bb = Bs[buf];
#pragma unroll
        for (int ks = 0; ks < 2; ks++) {
            uint32_t af[2][4], bf[4][2];
#pragma unroll
            for (int mt = 0; mt < 2; mt++) {
                int bm = wm * 32 + mt * 16 + g;
                af[mt][0] = Ab[(ks * 8 + tig) * 72 + bm];
                af[mt][1] = Ab[(ks * 8 + tig) * 72 + bm + 8];
                af[mt][2] = Ab[(ks * 8 + tig + 4) * 72 + bm];
                af[mt][3] = Ab[(ks * 8 + tig + 4) * 72 + bm + 8];
            }
#pragma unroll
            for (int nt = 0; nt < 4; nt++) {
                int bn = wn * 32 + nt * 8 + g;
                bf[nt][0] = Bb[(ks * 8 + tig) * 136 + bn];
                bf[nt][1] = Bb[(ks * 8 + tig + 4) * 136 + bn];
            }
#pragma unroll
            for (int mt = 0; mt < 2; mt++)
#pragma unroll
                for (int nt = 0; nt < 4; nt++)
                    mma_tf32(acc[mt][nt][0], acc[mt][nt][1], acc[mt][nt][2], acc[mt][nt][3],
                             af[mt][0], af[mt][1], af[mt][2], af[mt][3],
                             bf[nt][0], bf[nt][1]);
        }
        buf ^= 1;
    }

#pragma unroll
    for (int mt = 0; mt < 2; mt++) {
        int row = m0 + wm * 32 + mt * 16 + g;
#pragma unroll
        for (int nt = 0; nt < 4; nt++) {
            int col = n0 + wn * 32 + nt * 8 + tig * 2;
            *(float2*)(C + (long long)row * ldc + col) =
                make_float2(acc[mt][nt][0], acc[mt][nt][1]);
            *(float2*)(C + (long long)(row + 8) * ldc + col) =
                make_float2(acc[mt][nt][2], acc[mt][nt][3]);
        }
    }
}

// =====================================================================
// Fused attention (fp32). Epilogue rounds output to tf32 (feeds O GEMM).
// =====================================================================
#define ATT_SMEM_BYTES (55296 * 4)

__global__ __launch_bounds__(256) void attn_kernel(
    const float* __restrict__ Q, const float* __restrict__ Keys,
    const float* __restrict__ Vals, float* __restrict__ O)
{
    extern __shared__ float sm[];
    float* qs = sm;                    // [64][64]
    float* ks = qs + 64 * 64;          // [256][68]
    float* vs = ks + 256 * 68;         // [256][68]
    float* ps = vs + 256 * 68;         // [64][256]

    const int tid = threadIdx.x;
    const int qt = blockIdx.x;
    const int h  = blockIdx.y;
    const int b  = blockIdx.z;

    const long long qbase  = ((long long)b * SEQN + qt * 64) * DIMN + h * DHN;
    const long long kvbase = ((long long)b * KLR) * DIMN + h * DHN;

#pragma unroll
    for (int i = 0; i < 4; i++) {
        int idx = tid + i * 256;
        int r = idx >> 4, c4 = (idx & 15) * 4;
        *(float4*)&qs[r * 64 + c4] =
            *(const float4*)(Q + qbase + (long long)r * DIMN + c4);
    }
#pragma unroll
    for (int i = 0; i < 16; i++) {
        int idx = tid + i * 256;
        int r = idx >> 4, c4 = (idx & 15) * 4;
        *(float4*)&ks[r * 68 + c4] =
            *(const float4*)(Keys + kvbase + (long long)r * DIMN + c4);
        *(float4*)&vs[r * 68 + c4] =
            *(const float4*)(Vals + kvbase + (long long)r * DIMN + c4);
    }
    __syncthreads();

    float4 kr[16];
#pragma unroll
    for (int d = 0; d < 16; d++) kr[d] = *(const float4*)&ks[tid * 68 + d * 4];

    for (int r = 0; r < 64; r++) {
        float acc = 0.f;
#pragma unroll
        for (int d = 0; d < 16; d++) {
            float4 qv = *(const float4*)&qs[r * 64 + d * 4];
            acc = fmaf(qv.x, kr[d].x, acc);
            acc = fmaf(qv.y, kr[d].y, acc);
            acc = fmaf(qv.z, kr[d].z, acc);
            acc = fmaf(qv.w, kr[d].w, acc);
        }
        ps[r * 256 + tid] = acc * 0.125f;
    }
    __syncthreads();

    const int warp = tid >> 5, lane = tid & 31;
    for (int rr = 0; rr < 8; rr++) {
        int r = warp * 8 + rr;
        float v[8], mx = -1e30f;
#pragma unroll
        for (int j = 0; j < 8; j++) {
            v[j] = ps[r * 256 + lane + j * 32];
            mx = fmaxf(mx, v[j]);
        }
#pragma unroll
        for (int s = 16; s > 0; s >>= 1)
            mx = fmaxf(mx, __shfl_xor_sync(0xffffffffu, mx, s));
        float sum = 0.f;
#pragma unroll
        for (int j = 0; j < 8; j++) { v[j] = __expf(v[j] - mx); sum += v[j]; }
#pragma unroll
        for (int s = 16; s > 0; s >>= 1)
            sum += __shfl_xor_sync(0xffffffffu, sum, s);
        float inv = 1.f / sum;
#pragma unroll
        for (int j = 0; j < 8; j++)
            ps[r * 256 + lane + j * 32] = v[j] * inv;
    }
    __syncthreads();

    const int d  = tid & 63;
    const int r0 = (tid >> 6) * 16;
    float acc[16];
#pragma unroll
    for (int i = 0; i < 16; i++) acc[i] = 0.f;
    for (int c = 0; c < 256; c++) {
        float vv = vs[c * 68 + d];
#pragma unroll
        for (int i = 0; i < 16; i++)
            acc[i] = fmaf(ps[(r0 + i) * 256 + c], vv, acc[i]);
    }
#pragma unroll
    for (int i = 0; i < 16; i++)
        O[qbase + (long long)(r0 + i) * DIMN + d] = tf32r(acc[i]);
}

// =====================================================================
// launch
// =====================================================================
extern "C" void kernel_launch(void* const* d_in, const int* in_sizes, int n_in,
                              void* d_out, int out_size)
{
    (void)in_sizes; (void)n_in; (void)out_size;

    const float* x  = (const float*)d_in[0];
    const float* Wq = (const float*)d_in[1];
    const float* Wk = (const float*)d_in[2];
    const float* Wv = (const float*)d_in[3];
    const float* pk = (const float*)d_in[4];
    const float* pv = (const float*)d_in[5];
    const float* Wo = (const float*)d_in[6];
    const float* bo = (const float*)d_in[7];
    float* out = (float*)d_out;

    float *Q, *K, *V, *keys, *vals;
    float *xt, *wqt, *wkt, *wvt, *wot, *pkt, *pvt;
    cudaGetSymbolAddress((void**)&Q, g_Q);
    cudaGetSymbolAddress((void**)&K, g_K);
    cudaGetSymbolAddress((void**)&V, g_V);
    cudaGetSymbolAddress((void**)&keys, g_keys);
    cudaGetSymbolAddress((void**)&vals, g_vals);
    cudaGetSymbolAddress((void**)&xt, g_xt);
    cudaGetSymbolAddress((void**)&wqt, g_wqt);
    cudaGetSymbolAddress((void**)&wkt, g_wkt);
    cudaGetSymbolAddress((void**)&wvt, g_wvt);
    cudaGetSymbolAddress((void**)&wot, g_wot);
    cudaGetSymbolAddress((void**)&pkt, g_pkt);
    cudaGetSymbolAddress((void**)&pvt, g_pvt);
    float* AO = K;   // overlay: K dead after keys projection

    // 0) round inputs to tf32 once
    {
        int n4x = (M_TOK * DIMN) / 4;
        round_tf32_kernel<<<(n4x + 255) / 256, 256>>>(x, xt, n4x);
        int n4w = (DIMN * DIMN) / 4;
        round_tf32_kernel<<<(n4w + 255) / 256, 256>>>(Wq, wqt, n4w);
        round_tf32_kernel<<<(n4w + 255) / 256, 256>>>(Wk, wkt, n4w);
        round_tf32_kernel<<<(n4w + 255) / 256, 256>>>(Wv, wvt, n4w);
        round_tf32_kernel<<<(n4w + 255) / 256, 256>>>(Wo, wot, n4w);
        int n4p = (SEQN * KLR) / 4;
        round_tf32_kernel<<<(n4p + 255) / 256, 256>>>(pk, pkt, n4p);
        round_tf32_kernel<<<(n4p + 255) / 256, 256>>>(pv, pvt, n4p);
    }

    // 1) Q/K/V projections (pipelined TF32). K/V outputs rounded (feed TN).
    dim3 gbig(DIMN / 128, M_TOK / 128);
    gemm_nt_tf32<<<gbig, 256>>>(xt, wqt, nullptr, Q, DIMN, DIMN, DIMN, DIMN, 0, 0);
    gemm_nt_tf32<<<gbig, 256>>>(xt, wkt, nullptr, K, DIMN, DIMN, DIMN, DIMN, 0, 1);
    gemm_nt_tf32<<<gbig, 256>>>(xt, wvt, nullptr, V, DIMN, DIMN, DIMN, DIMN, 0, 1);

    // 2) low-rank sequence projection per batch (pipelined TF32)
    dim3 gproj(DIMN / 128, KLR / 64, BATCHN);
    gemm_tn_tf32<<<gproj, 256>>>(pkt, K, keys, SEQN, KLR, DIMN, DIMN,
                                 (long long)SEQN * DIMN, (long long)KLR * DIMN);
    gemm_tn_tf32<<<gproj, 256>>>(pvt, V, vals, SEQN, KLR, DIMN, DIMN,
                                 (long long)SEQN * DIMN, (long long)KLR * DIMN);

    // 3) fused attention (writes tf32-rounded AO over the K buffer)
    cudaFuncSetAttribute(attn_kernel,
                         cudaFuncAttributeMaxDynamicSharedMemorySize,
                         ATT_SMEM_BYTES);
    dim3 gatt(SEQN / 64, HEADSN, BATCHN);
    attn_kernel<<<gatt, 256, ATT_SMEM_BYTES>>>(Q, keys, vals, AO);

    // 4) output projection + bias (pipelined TF32)
    gemm_nt_tf32<<<gbig, 256>>>(AO, wot, bo, out, DIMN, DIMN, DIMN, DIMN, 1, 0);
}

// round 7
// speedup vs baseline: 2.7690x; 1.2411x over previous
#include <cuda_runtime.h>
#include <cstdint>

// ---------------- problem constants ----------------
#define M_TOK  16384     // BATCH * SEQ
#define DIMN   1024
#define KLR    256
#define BATCHN 4
#define SEQN   4096
#define HEADSN 16
#define DHN    64

// ---------------- scratch (device globals) ----------------
__device__ float g_Q[16384 * 1024];
__device__ float g_AO[16384 * 1024];
__device__ float g_keys[4 * 256 * 1024];
__device__ float g_vals[4 * 256 * 1024];
__device__ float g_xk[4 * 256 * 1024];    // pk^T x  (tf32-rounded)
__device__ float g_xv[4 * 256 * 1024];    // pv^T x  (tf32-rounded)
// tf32-rounded copies of inputs
__device__ float g_xt[16384 * 1024];
__device__ float g_wqt[1024 * 1024];
__device__ float g_wkt[1024 * 1024];
__device__ float g_wvt[1024 * 1024];
__device__ float g_wot[1024 * 1024];
__device__ float g_pkt[4096 * 256];
__device__ float g_pvt[4096 * 256];

// ---------------- tf32 helpers ----------------
__device__ __forceinline__ float tf32r(float f) {
    uint32_t u;
    asm("cvt.rna.tf32.f32 %0, %1;" : "=r"(u) : "f"(f));
    return __uint_as_float(u);
}

__device__ __forceinline__ void mma_tf32(
    float& c0, float& c1, float& c2, float& c3,
    uint32_t a0, uint32_t a1, uint32_t a2, uint32_t a3,
    uint32_t b0, uint32_t b1)
{
    asm volatile(
        "mma.sync.aligned.m16n8k8.row.col.f32.tf32.tf32.f32 "
        "{%0,%1,%2,%3}, {%4,%5,%6,%7}, {%8,%9}, {%0,%1,%2,%3};\n"
        : "+f"(c0), "+f"(c1), "+f"(c2), "+f"(c3)
        : "r"(a0), "r"(a1), "r"(a2), "r"(a3), "r"(b0), "r"(b1));
}

__device__ __forceinline__ void cp16(uint32_t smem, const void* g) {
    asm volatile("cp.async.cg.shared.global [%0], [%1], 16;\n"
                 :: "r"(smem), "l"(g));
}
__device__ __forceinline__ void cp_commit() {
    asm volatile("cp.async.commit_group;\n");
}
__device__ __forceinline__ void cp_wait0() {
    asm volatile("cp.async.wait_group 0;\n");
}

// ---------------- prep: round to tf32 (RNA) ----------------
__global__ __launch_bounds__(256) void round_tf32_kernel(
    const float* __restrict__ in, float* __restrict__ out, int n4)
{
    int i = blockIdx.x * 256 + threadIdx.x;
    if (i < n4) {
        float4 v = ((const float4*)in)[i];
        v.x = tf32r(v.x); v.y = tf32r(v.y); v.z = tf32r(v.z); v.w = tf32r(v.w);
        ((float4*)out)[i] = v;
    }
}

// =====================================================================
// NT TF32 GEMM (pipelined): C[m,n] = sum_k A[m][k]*B[n][k] (+bias)
// Inputs pre-rounded. Block 128x128, BK=16, 256 thr, double-buffered.
// =====================================================================
__global__ __launch_bounds__(256, 2) void gemm_nt_tf32(
    const float* __restrict__ A, const float* __restrict__ B,
    const float* __restrict__ bias, float* __restrict__ C,
    int K, int lda, int ldb, int ldc, int add_bias, int round_out)
{
    __shared__ uint32_t As[2][128 * 20];
    __shared__ uint32_t Bs[2][128 * 20];

    const int tid  = threadIdx.x;
    const int wid  = tid >> 5, lane = tid & 31;
    const int g    = lane >> 2, tig = lane & 3;
    const int wm   = wid >> 2;
    const int wn   = wid & 3;
    const int m0   = blockIdx.y * 128;
    const int n0   = blockIdx.x * 128;

    const int lrow = tid >> 1;
    const int lkg  = (tid & 1) * 8;
    const float* Ag = A + (long long)(m0 + lrow) * lda + lkg;
    const float* Bg = B + (long long)(n0 + lrow) * ldb + lkg;

    const uint32_t sa0 = (uint32_t)__cvta_generic_to_shared(&As[0][lrow * 20 + lkg]);
    const uint32_t sa1 = (uint32_t)__cvta_generic_to_shared(&As[1][lrow * 20 + lkg]);
    const uint32_t sb0 = (uint32_t)__cvta_generic_to_shared(&Bs[0][lrow * 20 + lkg]);
    const uint32_t sb1 = (uint32_t)__cvta_generic_to_shared(&Bs[1][lrow * 20 + lkg]);

    float acc[4][4][4];
#pragma unroll
    for (int mt = 0; mt < 4; mt++)
#pragma unroll
        for (int nt = 0; nt < 4; nt++)
#pragma unroll
            for (int r = 0; r < 4; r++) acc[mt][nt][r] = 0.f;

    cp16(sa0, Ag);      cp16(sa0 + 16, Ag + 4);
    cp16(sb0, Bg);      cp16(sb0 + 16, Bg + 4);
    cp_commit();

    int buf = 0;
    for (int k0 = 0; k0 < K; k0 += 16) {
        cp_wait0();
        __syncthreads();
        if (k0 + 16 < K) {
            uint32_t da = buf ? sa0 : sa1;
            uint32_t db = buf ? sb0 : sb1;
            cp16(da, Ag + k0 + 16);      cp16(da + 16, Ag + k0 + 20);
            cp16(db, Bg + k0 + 16);      cp16(db + 16, Bg + k0 + 20);
            cp_commit();
        }
        const uint32_t* Ab = As[buf];
        const uint32_t* Bb = Bs[buf];
#pragma unroll
        for (int ks = 0; ks < 2; ks++) {
            uint32_t af[4][4], bf[4][2];
#pragma unroll
            for (int mt = 0; mt < 4; mt++) {
                int mr = wm * 64 + mt * 16 + g;
                af[mt][0] = Ab[mr * 20 + ks * 8 + tig];
                af[mt][1] = Ab[(mr + 8) * 20 + ks * 8 + tig];
                af[mt][2] = Ab[mr * 20 + ks * 8 + tig + 4];
                af[mt][3] = Ab[(mr + 8) * 20 + ks * 8 + tig + 4];
            }
#pragma unroll
            for (int nt = 0; nt < 4; nt++) {
                int nr = wn * 32 + nt * 8 + g;
                bf[nt][0] = Bb[nr * 20 + ks * 8 + tig];
                bf[nt][1] = Bb[nr * 20 + ks * 8 + tig + 4];
            }
#pragma unroll
            for (int mt = 0; mt < 4; mt++)
#pragma unroll
                for (int nt = 0; nt < 4; nt++)
                    mma_tf32(acc[mt][nt][0], acc[mt][nt][1], acc[mt][nt][2], acc[mt][nt][3],
                             af[mt][0], af[mt][1], af[mt][2], af[mt][3],
                             bf[nt][0], bf[nt][1]);
        }
        buf ^= 1;
    }

#pragma unroll
    for (int nt = 0; nt < 4; nt++) {
        int col = n0 + wn * 32 + nt * 8 + tig * 2;
        float b0 = 0.f, b1 = 0.f;
        if (add_bias) { b0 = bias[col]; b1 = bias[col + 1]; }
#pragma unroll
        for (int mt = 0; mt < 4; mt++) {
            int row = m0 + wm * 64 + mt * 16 + g;
            float v00 = acc[mt][nt][0] + b0, v01 = acc[mt][nt][1] + b1;
            float v10 = acc[mt][nt][2] + b0, v11 = acc[mt][nt][3] + b1;
            if (round_out) {
                v00 = tf32r(v00); v01 = tf32r(v01);
                v10 = tf32r(v10); v11 = tf32r(v11);
            }
            *(float2*)(C + (long long)row * ldc + col) = make_float2(v00, v01);
            *(float2*)(C + (long long)(row + 8) * ldc + col) = make_float2(v10, v11);
        }
    }
}

// =====================================================================
// TN TF32 GEMM (batched z, pipelined): C[m,n] = sum_p A[p][m]*B[p][n]
// round_out: round C to tf32 (xk/xv feed the small NT GEMMs).
// =====================================================================
__global__ __launch_bounds__(256) void gemm_tn_tf32(
    const float* __restrict__ A, const float* __restrict__ B, float* __restrict__ C,
    int P, int lda, int ldb, int ldc, long long strideB, long long strideC,
    int round_out)
{
    B += (long long)blockIdx.z * strideB;
    C += (long long)blockIdx.z * strideC;

    __shared__ uint32_t As[2][16 * 72];
    __shared__ uint32_t Bs[2][16 * 136];

    const int tid  = threadIdx.x;
    const int wid  = tid >> 5, lane = tid & 31;
    const int g    = lane >> 2, tig = lane & 3;
    const int wm   = wid >> 2;
    const int wn   = wid & 3;
    const int m0   = blockIdx.y * 64;
    const int n0   = blockIdx.x * 128;

    const int lp   = tid >> 4;
    const int lma  = (tid & 15) * 4;
    const int lnb  = (tid & 15) * 8;
    const float* Ag = A + (long long)lp * lda + m0 + lma;
    const float* Bg = B + (long long)lp * ldb + n0 + lnb;

    const uint32_t sa0 = (uint32_t)__cvta_generic_to_shared(&As[0][lp * 72 + lma]);
    const uint32_t sa1 = (uint32_t)__cvta_generic_to_shared(&As[1][lp * 72 + lma]);
    const uint32_t sb0 = (uint32_t)__cvta_generic_to_shared(&Bs[0][lp * 136 + lnb]);
    const uint32_t sb1 = (uint32_t)__cvta_generic_to_shared(&Bs[1][lp * 136 + lnb]);

    float acc[2][4][4];
#pragma unroll
    for (int mt = 0; mt < 2; mt++)
#pragma unroll
        for (int nt = 0; nt < 4; nt++)
#pragma unroll
            for (int r = 0; r < 4; r++) acc[mt][nt][r] = 0.f;

    cp16(sa0, Ag);
    cp16(sb0, Bg);   cp16(sb0 + 16, Bg + 4);
    cp_commit();

    int buf = 0;
    for (int p0 = 0; p0 < P; p0 += 16) {
        cp_wait0();
        __syncthreads();
        if (p0 + 16 < P) {
            uint32_t da = buf ? sa0 : sa1;
            uint32_t db = buf ? sb0 : sb1;
            const float* An = Ag + (long long)(p0 + 16) * lda;
            const float* Bn = Bg + (long long)(p0 + 16) * ldb;
            cp16(da, An);
            cp16(db, Bn);   cp16(db + 16, Bn + 4);
            cp_commit();
        }
        const uint32_t* Ab = As[buf];
        const uint32_t* Bb = Bs[buf];
#pragma unroll
        for (int ks = 0; ks < 2; ks++) {
            uint32_t af[2][4], bf[4][2];
#pragma unroll
            for (int mt = 0; mt < 2; mt++) {
                int bm = wm * 32 + mt * 16 + g;
                af[mt][0] = Ab[(ks * 8 + tig) * 72 + bm];
                af[mt][1] = Ab[(ks * 8 + tig) * 72 + bm + 8];
                af[mt][2] = Ab[(ks * 8 + tig + 4) * 72 + bm];
                af[mt][3] = Ab[(ks * 8 + tig + 4) * 72 + bm + 8];
            }
#pragma unroll
            for (int nt = 0; nt < 4; nt++) {
                int bn = wn * 32 + nt * 8 + g;
                bf[nt][0] = Bb[(ks * 8 + tig) * 136 + bn];
                bf[nt][1] = Bb[(ks * 8 + tig + 4) * 136 + bn];
            }
#pragma unroll
            for (int mt = 0; mt < 2; mt++)
#pragma unroll
                for (int nt = 0; nt < 4; nt++)
                    mma_tf32(acc[mt][nt][0], acc[mt][nt][1], acc[mt][nt][2], acc[mt][nt][3],
                             af[mt][0], af[mt][1], af[mt][2], af[mt][3],
                             bf[nt][0], bf[nt][1]);
        }
        buf ^= 1;
    }

#pragma unroll
    for (int mt = 0; mt < 2; mt++) {
        int row = m0 + wm * 32 + mt * 16 + g;
#pragma unroll
        for (int nt = 0; nt < 4; nt++) {
            int col = n0 + wn * 32 + nt * 8 + tig * 2;
            float v00 = acc[mt][nt][0], v01 = acc[mt][nt][1];
            float v10 = acc[mt][nt][2], v11 = acc[mt][nt][3];
            if (round_out) {
                v00 = tf32r(v00); v01 = tf32r(v01);
                v10 = tf32r(v10); v11 = tf32r(v11);
            }
            *(float2*)(C + (long long)row * ldc + col) = make_float2(v00, v01);
            *(float2*)(C + (long long)(row + 8) * ldc + col) = make_float2(v10, v11);
        }
    }
}

// =====================================================================
// Fused attention (fp32). Epilogue rounds output to tf32 (feeds O GEMM).
// =====================================================================
#define ATT_SMEM_BYTES (55296 * 4)

__global__ __launch_bounds__(256) void attn_kernel(
    const float* __restrict__ Q, const float* __restrict__ Keys,
    const float* __restrict__ Vals, float* __restrict__ O)
{
    extern __shared__ float sm[];
    float* qs = sm;                    // [64][64]
    float* ks = qs + 64 * 64;          // [256][68]
    float* vs = ks + 256 * 68;         // [256][68]
    float* ps = vs + 256 * 68;         // [64][256]

    const int tid = threadIdx.x;
    const int qt = blockIdx.x;
    const int h  = blockIdx.y;
    const int b  = blockIdx.z;

    const long long qbase  = ((long long)b * SEQN + qt * 64) * DIMN + h * DHN;
    const long long kvbase = ((long long)b * KLR) * DIMN + h * DHN;

#pragma unroll
    for (int i = 0; i < 4; i++) {
        int idx = tid + i * 256;
        int r = idx >> 4, c4 = (idx & 15) * 4;
        *(float4*)&qs[r * 64 + c4] =
            *(const float4*)(Q + qbase + (long long)r * DIMN + c4);
    }
#pragma unroll
    for (int i = 0; i < 16; i++) {
        int idx = tid + i * 256;
        int r = idx >> 4, c4 = (idx & 15) * 4;
        *(float4*)&ks[r * 68 + c4] =
            *(const float4*)(Keys + kvbase + (long long)r * DIMN + c4);
        *(float4*)&vs[r * 68 + c4] =
            *(const float4*)(Vals + kvbase + (long long)r * DIMN + c4);
    }
    __syncthreads();

    float4 kr[16];
#pragma unroll
    for (int d = 0; d < 16; d++) kr[d] = *(const float4*)&ks[tid * 68 + d * 4];

    for (int r = 0; r < 64; r++) {
        float acc = 0.f;
#pragma unroll
        for (int d = 0; d < 16; d++) {
            float4 qv = *(const float4*)&qs[r * 64 + d * 4];
            acc = fmaf(qv.x, kr[d].x, acc);
            acc = fmaf(qv.y, kr[d].y, acc);
            acc = fmaf(qv.z, kr[d].z, acc);
            acc = fmaf(qv.w, kr[d].w, acc);
        }
        ps[r * 256 + tid] = acc * 0.125f;
    }
    __syncthreads();

    const int warp = tid >> 5, lane = tid & 31;
    for (int rr = 0; rr < 8; rr++) {
        int r = warp * 8 + rr;
        float v[8], mx = -1e30f;
#pragma unroll
        for (int j = 0; j < 8; j++) {
            v[j] = ps[r * 256 + lane + j * 32];
            mx = fmaxf(mx, v[j]);
        }
#pragma unroll
        for (int s = 16; s > 0; s >>= 1)
            mx = fmaxf(mx, __shfl_xor_sync(0xffffffffu, mx, s));
        float sum = 0.f;
#pragma unroll
        for (int j = 0; j < 8; j++) { v[j] = __expf(v[j] - mx); sum += v[j]; }
#pragma unroll
        for (int s = 16; s > 0; s >>= 1)
            sum += __shfl_xor_sync(0xffffffffu, sum, s);
        float inv = 1.f / sum;
#pragma unroll
        for (int j = 0; j < 8; j++)
            ps[r * 256 + lane + j * 32] = v[j] * inv;
    }
    __syncthreads();

    const int d  = tid & 63;
    const int r0 = (tid >> 6) * 16;
    float acc[16];
#pragma unroll
    for (int i = 0; i < 16; i++) acc[i] = 0.f;
    for (int c = 0; c < 256; c++) {
        float vv = vs[c * 68 + d];
#pragma unroll
        for (int i = 0; i < 16; i++)
            acc[i] = fmaf(ps[(r0 + i) * 256 + c], vv, acc[i]);
    }
#pragma unroll
    for (int i = 0; i < 16; i++)
        O[qbase + (long long)(r0 + i) * DIMN + d] = tf32r(acc[i]);
}

// =====================================================================
// launch
// =====================================================================
extern "C" void kernel_launch(void* const* d_in, const int* in_sizes, int n_in,
                              void* d_out, int out_size)
{
    (void)in_sizes; (void)n_in; (void)out_size;

    const float* x  = (const float*)d_in[0];
    const float* Wq = (const float*)d_in[1];
    const float* Wk = (const float*)d_in[2];
    const float* Wv = (const float*)d_in[3];
    const float* pk = (const float*)d_in[4];
    const float* pv = (const float*)d_in[5];
    const float* Wo = (const float*)d_in[6];
    const float* bo = (const float*)d_in[7];
    float* out = (float*)d_out;

    float *Q, *AO, *keys, *vals, *xk, *xv;
    float *xt, *wqt, *wkt, *wvt, *wot, *pkt, *pvt;
    cudaGetSymbolAddress((void**)&Q, g_Q);
    cudaGetSymbolAddress((void**)&AO, g_AO);
    cudaGetSymbolAddress((void**)&keys, g_keys);
    cudaGetSymbolAddress((void**)&vals, g_vals);
    cudaGetSymbolAddress((void**)&xk, g_xk);
    cudaGetSymbolAddress((void**)&xv, g_xv);
    cudaGetSymbolAddress((void**)&xt, g_xt);
    cudaGetSymbolAddress((void**)&wqt, g_wqt);
    cudaGetSymbolAddress((void**)&wkt, g_wkt);
    cudaGetSymbolAddress((void**)&wvt, g_wvt);
    cudaGetSymbolAddress((void**)&wot, g_wot);
    cudaGetSymbolAddress((void**)&pkt, g_pkt);
    cudaGetSymbolAddress((void**)&pvt, g_pvt);

    // 0) round inputs to tf32 once
    {
        int n4x = (M_TOK * DIMN) / 4;
        round_tf32_kernel<<<(n4x + 255) / 256, 256>>>(x, xt, n4x);
        int n4w = (DIMN * DIMN) / 4;
        round_tf32_kernel<<<(n4w + 255) / 256, 256>>>(Wq, wqt, n4w);
        round_tf32_kernel<<<(n4w + 255) / 256, 256>>>(Wk, wkt, n4w);
        round_tf32_kernel<<<(n4w + 255) / 256, 256>>>(Wv, wvt, n4w);
        round_tf32_kernel<<<(n4w + 255) / 256, 256>>>(Wo, wot, n4w);
        int n4p = (SEQN * KLR) / 4;
        round_tf32_kernel<<<(n4p + 255) / 256, 256>>>(pk, pkt, n4p);
        round_tf32_kernel<<<(n4p + 255) / 256, 256>>>(pv, pvt, n4p);
    }

    // 1) Q projection (full-size NT)
    dim3 gbig(DIMN / 128, M_TOK / 128);
    gemm_nt_tf32<<<gbig, 256>>>(xt, wqt, nullptr, Q, DIMN, DIMN, DIMN, DIMN, 0, 0);

    // 2) sequence projection of x FIRST (algebraic reorder):
    //    xk[b,k,d] = sum_n pk[n,k] * x[b,n,d]   (tf32-rounded out)
    dim3 gproj(DIMN / 128, KLR / 64, BATCHN);
    gemm_tn_tf32<<<gproj, 256>>>(pkt, xt, xk, SEQN, KLR, DIMN, DIMN,
                                 (long long)SEQN * DIMN, (long long)KLR * DIMN, 1);
    gemm_tn_tf32<<<gproj, 256>>>(pvt, xt, xv, SEQN, KLR, DIMN, DIMN,
                                 (long long)SEQN * DIMN, (long long)KLR * DIMN, 1);

    // 3) small NT GEMMs: keys = xk · Wk^T, vals = xv · Wv^T  (M = 4*256 = 1024)
    dim3 gsmall(DIMN / 128, (BATCHN * KLR) / 128);
    gemm_nt_tf32<<<gsmall, 256>>>(xk, wkt, nullptr, keys, DIMN, DIMN, DIMN, DIMN, 0, 0);
    gemm_nt_tf32<<<gsmall, 256>>>(xv, wvt, nullptr, vals, DIMN, DIMN, DIMN, DIMN, 0, 0);

    // 4) fused attention (tf32-rounded AO)
    cudaFuncSetAttribute(attn_kernel,
                         cudaFuncAttributeMaxDynamicSharedMemorySize,
                         ATT_SMEM_BYTES);
    dim3 gatt(SEQN / 64, HEADSN, BATCHN);
    attn_kernel<<<gatt, 256, ATT_SMEM_BYTES>>>(Q, keys, vals, AO);

    // 5) output projection + bias
    gemm_nt_tf32<<<gbig, 256>>>(AO, wot, bo, out, DIMN, DIMN, DIMN, DIMN, 1, 0);
}

// round 8
// speedup vs baseline: 4.3454x; 1.5693x over previous
#include <cuda_runtime.h>
#include <cstdint>

// ---------------- problem constants ----------------
#define M_TOK  16384     // BATCH * SEQ
#define DIMN   1024
#define KLR    256
#define BATCHN 4
#define SEQN   4096
#define HEADSN 16
#define DHN    64

// ---------------- scratch (device globals) ----------------
__device__ float g_Q[16384 * 1024];
__device__ float g_AO[16384 * 1024];
__device__ float g_keys[4 * 256 * 1024];
__device__ float g_vals[4 * 256 * 1024];
__device__ float g_xk[4 * 256 * 1024];
__device__ float g_xv[4 * 256 * 1024];
__device__ float g_xt[16384 * 1024];
__device__ float g_wqt[1024 * 1024];
__device__ float g_wkt[1024 * 1024];
__device__ float g_wvt[1024 * 1024];
__device__ float g_wot[1024 * 1024];
__device__ float g_pkt[4096 * 256];
__device__ float g_pvt[4096 * 256];

// ---------------- tf32 helpers ----------------
__device__ __forceinline__ float tf32r(float f) {
    uint32_t u;
    asm("cvt.rna.tf32.f32 %0, %1;" : "=r"(u) : "f"(f));
    return __uint_as_float(u);
}

__device__ __forceinline__ void mma_tf32(
    float& c0, float& c1, float& c2, float& c3,
    uint32_t a0, uint32_t a1, uint32_t a2, uint32_t a3,
    uint32_t b0, uint32_t b1)
{
    asm volatile(
        "mma.sync.aligned.m16n8k8.row.col.f32.tf32.tf32.f32 "
        "{%0,%1,%2,%3}, {%4,%5,%6,%7}, {%8,%9}, {%0,%1,%2,%3};\n"
        : "+f"(c0), "+f"(c1), "+f"(c2), "+f"(c3)
        : "r"(a0), "r"(a1), "r"(a2), "r"(a3), "r"(b0), "r"(b1));
}

__device__ __forceinline__ void cp16(uint32_t smem, const void* g) {
    asm volatile("cp.async.cg.shared.global [%0], [%1], 16;\n"
                 :: "r"(smem), "l"(g));
}
__device__ __forceinline__ void cp_commit() {
    asm volatile("cp.async.commit_group;\n");
}
__device__ __forceinline__ void cp_wait0() {
    asm volatile("cp.async.wait_group 0;\n");
}

// ---------------- prep: round to tf32 (RNA) ----------------
__global__ __launch_bounds__(256) void round_tf32_kernel(
    const float* __restrict__ in, float* __restrict__ out, int n4)
{
    int i = blockIdx.x * 256 + threadIdx.x;
    if (i < n4) {
        float4 v = ((const float4*)in)[i];
        v.x = tf32r(v.x); v.y = tf32r(v.y); v.z = tf32r(v.z); v.w = tf32r(v.w);
        ((float4*)out)[i] = v;
    }
}

// =====================================================================
// NT TF32 GEMM (pipelined): C[m,n] = sum_k A[m][k]*B[n][k] (+bias)
// =====================================================================
__global__ __launch_bounds__(256, 2) void gemm_nt_tf32(
    const float* __restrict__ A, const float* __restrict__ B,
    const float* __restrict__ bias, float* __restrict__ C,
    int K, int lda, int ldb, int ldc, int add_bias, int round_out)
{
    __shared__ uint32_t As[2][128 * 20];
    __shared__ uint32_t Bs[2][128 * 20];

    const int tid  = threadIdx.x;
    const int wid  = tid >> 5, lane = tid & 31;
    const int g    = lane >> 2, tig = lane & 3;
    const int wm   = wid >> 2;
    const int wn   = wid & 3;
    const int m0   = blockIdx.y * 128;
    const int n0   = blockIdx.x * 128;

    const int lrow = tid >> 1;
    const int lkg  = (tid & 1) * 8;
    const float* Ag = A + (long long)(m0 + lrow) * lda + lkg;
    const float* Bg = B + (long long)(n0 + lrow) * ldb + lkg;

    const uint32_t sa0 = (uint32_t)__cvta_generic_to_shared(&As[0][lrow * 20 + lkg]);
    const uint32_t sa1 = (uint32_t)__cvta_generic_to_shared(&As[1][lrow * 20 + lkg]);
    const uint32_t sb0 = (uint32_t)__cvta_generic_to_shared(&Bs[0][lrow * 20 + lkg]);
    const uint32_t sb1 = (uint32_t)__cvta_generic_to_shared(&Bs[1][lrow * 20 + lkg]);

    float acc[4][4][4];
#pragma unroll
    for (int mt = 0; mt < 4; mt++)
#pragma unroll
        for (int nt = 0; nt < 4; nt++)
#pragma unroll
            for (int r = 0; r < 4; r++) acc[mt][nt][r] = 0.f;

    cp16(sa0, Ag);      cp16(sa0 + 16, Ag + 4);
    cp16(sb0, Bg);      cp16(sb0 + 16, Bg + 4);
    cp_commit();

    int buf = 0;
    for (int k0 = 0; k0 < K; k0 += 16) {
        cp_wait0();
        __syncthreads();
        if (k0 + 16 < K) {
            uint32_t da = buf ? sa0 : sa1;
            uint32_t db = buf ? sb0 : sb1;
            cp16(da, Ag + k0 + 16);      cp16(da + 16, Ag + k0 + 20);
            cp16(db, Bg + k0 + 16);      cp16(db + 16, Bg + k0 + 20);
            cp_commit();
        }
        const uint32_t* Ab = As[buf];
        const uint32_t* Bb = Bs[buf];
#pragma unroll
        for (int ks = 0; ks < 2; ks++) {
            uint32_t af[4][4], bf[4][2];
#pragma unroll
            for (int mt = 0; mt < 4; mt++) {
                int mr = wm * 64 + mt * 16 + g;
                af[mt][0] = Ab[mr * 20 + ks * 8 + tig];
                af[mt][1] = Ab[(mr + 8) * 20 + ks * 8 + tig];
                af[mt][2] = Ab[mr * 20 + ks * 8 + tig + 4];
                af[mt][3] = Ab[(mr + 8) * 20 + ks * 8 + tig + 4];
            }
#pragma unroll
            for (int nt = 0; nt < 4; nt++) {
                int nr = wn * 32 + nt * 8 + g;
                bf[nt][0] = Bb[nr * 20 + ks * 8 + tig];
                bf[nt][1] = Bb[nr * 20 + ks * 8 + tig + 4];
            }
#pragma unroll
            for (int mt = 0; mt < 4; mt++)
#pragma unroll
                for (int nt = 0; nt < 4; nt++)
                    mma_tf32(acc[mt][nt][0], acc[mt][nt][1], acc[mt][nt][2], acc[mt][nt][3],
                             af[mt][0], af[mt][1], af[mt][2], af[mt][3],
                             bf[nt][0], bf[nt][1]);
        }
        buf ^= 1;
    }

#pragma unroll
    for (int nt = 0; nt < 4; nt++) {
        int col = n0 + wn * 32 + nt * 8 + tig * 2;
        float b0 = 0.f, b1 = 0.f;
        if (add_bias) { b0 = bias[col]; b1 = bias[col + 1]; }
#pragma unroll
        for (int mt = 0; mt < 4; mt++) {
            int row = m0 + wm * 64 + mt * 16 + g;
            float v00 = acc[mt][nt][0] + b0, v01 = acc[mt][nt][1] + b1;
            float v10 = acc[mt][nt][2] + b0, v11 = acc[mt][nt][3] + b1;
            if (round_out) {
                v00 = tf32r(v00); v01 = tf32r(v01);
                v10 = tf32r(v10); v11 = tf32r(v11);
            }
            *(float2*)(C + (long long)row * ldc + col) = make_float2(v00, v01);
            *(float2*)(C + (long long)(row + 8) * ldc + col) = make_float2(v10, v11);
        }
    }
}

// =====================================================================
// TN TF32 GEMM (batched z, pipelined): C[m,n] = sum_p A[p][m]*B[p][n]
// =====================================================================
__global__ __launch_bounds__(256) void gemm_tn_tf32(
    const float* __restrict__ A, const float* __restrict__ B, float* __restrict__ C,
    int P, int lda, int ldb, int ldc, long long strideB, long long strideC,
    int round_out)
{
    B += (long long)blockIdx.z * strideB;
    C += (long long)blockIdx.z * strideC;

    __shared__ uint32_t As[2][16 * 72];
    __shared__ uint32_t Bs[2][16 * 136];

    const int tid  = threadIdx.x;
    const int wid  = tid >> 5, lane = tid & 31;
    const int g    = lane >> 2, tig = lane & 3;
    const int wm   = wid >> 2;
    const int wn   = wid & 3;
    const int m0   = blockIdx.y * 64;
    const int n0   = blockIdx.x * 128;

    const int lp   = tid >> 4;
    const int lma  = (tid & 15) * 4;
    const int lnb  = (tid & 15) * 8;
    const float* Ag = A + (long long)lp * lda + m0 + lma;
    const float* Bg = B + (long long)lp * ldb + n0 + lnb;

    const uint32_t sa0 = (uint32_t)__cvta_generic_to_shared(&As[0][lp * 72 + lma]);
    const uint32_t sa1 = (uint32_t)__cvta_generic_to_shared(&As[1][lp * 72 + lma]);
    const uint32_t sb0 = (uint32_t)__cvta_generic_to_shared(&Bs[0][lp * 136 + lnb]);
    const uint32_t sb1 = (uint32_t)__cvta_generic_to_shared(&Bs[1][lp * 136 + lnb]);

    float acc[2][4][4];
#pragma unroll
    for (int mt = 0; mt < 2; mt++)
#pragma unroll
        for (int nt = 0; nt < 4; nt++)
#pragma unroll
            for (int r = 0; r < 4; r++) acc[mt][nt][r] = 0.f;

    cp16(sa0, Ag);
    cp16(sb0, Bg);   cp16(sb0 + 16, Bg + 4);
    cp_commit();

    int buf = 0;
    for (int p0 = 0; p0 < P; p0 += 16) {
        cp_wait0();
        __syncthreads();
        if (p0 + 16 < P) {
            uint32_t da = buf ? sa0 : sa1;
            uint32_t db = buf ? sb0 : sb1;
            const float* An = Ag + (long long)(p0 + 16) * lda;
            const float* Bn = Bg + (long long)(p0 + 16) * ldb;
            cp16(da, An);
            cp16(db, Bn);   cp16(db + 16, Bn + 4);
            cp_commit();
        }
        const uint32_t* Ab = As[buf];
        const uint32_t* Bb = Bs[buf];
#pragma unroll
        for (int ks = 0; ks < 2; ks++) {
            uint32_t af[2][4], bf[4][2];
#pragma unroll
            for (int mt = 0; mt < 2; mt++) {
                int bm = wm * 32 + mt * 16 + g;
                af[mt][0] = Ab[(ks * 8 + tig) * 72 + bm];
                af[mt][1] = Ab[(ks * 8 + tig) * 72 + bm + 8];
                af[mt][2] = Ab[(ks * 8 + tig + 4) * 72 + bm];
                af[mt][3] = Ab[(ks * 8 + tig + 4) * 72 + bm + 8];
            }
#pragma unroll
            for (int nt = 0; nt < 4; nt++) {
                int bn = wn * 32 + nt * 8 + g;
                bf[nt][0] = Bb[(ks * 8 + tig) * 136 + bn];
                bf[nt][1] = Bb[(ks * 8 + tig + 4) * 136 + bn];
            }
#pragma unroll
            for (int mt = 0; mt < 2; mt++)
#pragma unroll
                for (int nt = 0; nt < 4; nt++)
                    mma_tf32(acc[mt][nt][0], acc[mt][nt][1], acc[mt][nt][2], acc[mt][nt][3],
                             af[mt][0], af[mt][1], af[mt][2], af[mt][3],
                             bf[nt][0], bf[nt][1]);
        }
        buf ^= 1;
    }

#pragma unroll
    for (int mt = 0; mt < 2; mt++) {
        int row = m0 + wm * 32 + mt * 16 + g;
#pragma unroll
        for (int nt = 0; nt < 4; nt++) {
            int col = n0 + wn * 32 + nt * 8 + tig * 2;
            float v00 = acc[mt][nt][0], v01 = acc[mt][nt][1];
            float v10 = acc[mt][nt][2], v11 = acc[mt][nt][3];
            if (round_out) {
                v00 = tf32r(v00); v01 = tf32r(v01);
                v10 = tf32r(v10); v11 = tf32r(v11);
            }
            *(float2*)(C + (long long)row * ldc + col) = make_float2(v00, v01);
            *(float2*)(C + (long long)(row + 8) * ldc + col) = make_float2(v10, v11);
        }
    }
}

// =====================================================================
// Fused attention, TF32 tensor cores for S=Q·K^T and O=P·V.
// Per (b, h, 64-row q tile). Q/keys/vals arrive tf32-rounded.
// smem floats: qs[64][68], ks[256][68], vs[256][72], ps[64][260]
//            = 4352 + 17408 + 18432 + 16640 = 56832 floats = 227328 B
// =====================================================================
#define ATT_SMEM_BYTES (56832 * 4)

__global__ __launch_bounds__(256) void attn_kernel(
    const float* __restrict__ Q, const float* __restrict__ Keys,
    const float* __restrict__ Vals, float* __restrict__ O)
{
    extern __shared__ float sm[];
    float* qs = sm;                     // [64][68]
    float* ks = qs + 64 * 68;           // [256][68]
    float* vs = ks + 256 * 68;          // [256][72]
    float* ps = vs + 256 * 72;          // [64][260]

    const int tid = threadIdx.x;
    const int wid = tid >> 5, lane = tid & 31;
    const int g   = lane >> 2, tig = lane & 3;
    const int wm  = wid >> 2;           // 0..1
    const int wn  = wid & 3;            // 0..3
    const int qt = blockIdx.x;
    const int h  = blockIdx.y;
    const int b  = blockIdx.z;

    const long long qbase  = ((long long)b * SEQN + qt * 64) * DIMN + h * DHN;
    const long long kvbase = ((long long)b * KLR) * DIMN + h * DHN;

    // loads (all tf32-rounded already)
#pragma unroll
    for (int i = 0; i < 4; i++) {
        int idx = tid + i * 256;                 // 0..1023
        int r = idx >> 4, c4 = (idx & 15) * 4;
        *(float4*)&qs[r * 68 + c4] =
            *(const float4*)(Q + qbase + (long long)r * DIMN + c4);
    }
#pragma unroll
    for (int i = 0; i < 16; i++) {
        int idx = tid + i * 256;                 // 0..4095
        int r = idx >> 4, c4 = (idx & 15) * 4;
        *(float4*)&ks[r * 68 + c4] =
            *(const float4*)(Keys + kvbase + (long long)r * DIMN + c4);
        *(float4*)&vs[r * 72 + c4] =
            *(const float4*)(Vals + kvbase + (long long)r * DIMN + c4);
    }
    __syncthreads();

    // ---- S = Q·K^T : warp tile 32(m) x 64(n), K=64 ----
    {
        float sacc[2][8][4];
#pragma unroll
        for (int mt = 0; mt < 2; mt++)
#pragma unroll
            for (int nt = 0; nt < 8; nt++)
#pragma unroll
                for (int r = 0; r < 4; r++) sacc[mt][nt][r] = 0.f;

        const uint32_t* qsu = (const uint32_t*)qs;
        const uint32_t* ksu = (const uint32_t*)ks;
#pragma unroll
        for (int kk = 0; kk < 8; kk++) {
            int k = kk * 8;
            uint32_t af[2][4], bf[8][2];
#pragma unroll
            for (int mt = 0; mt < 2; mt++) {
                int row = wm * 32 + mt * 16 + g;
                af[mt][0] = qsu[row * 68 + k + tig];
                af[mt][1] = qsu[(row + 8) * 68 + k + tig];
                af[mt][2] = qsu[row * 68 + k + tig + 4];
                af[mt][3] = qsu[(row + 8) * 68 + k + tig + 4];
            }
#pragma unroll
            for (int nt = 0; nt < 8; nt++) {
                int nrow = wn * 64 + nt * 8 + g;
                bf[nt][0] = ksu[nrow * 68 + k + tig];
                bf[nt][1] = ksu[nrow * 68 + k + tig + 4];
            }
#pragma unroll
            for (int mt = 0; mt < 2; mt++)
#pragma unroll
                for (int nt = 0; nt < 8; nt++)
                    mma_tf32(sacc[mt][nt][0], sacc[mt][nt][1], sacc[mt][nt][2], sacc[mt][nt][3],
                             af[mt][0], af[mt][1], af[mt][2], af[mt][3],
                             bf[nt][0], bf[nt][1]);
        }
        // store scaled S to ps (fp32)
#pragma unroll
        for (int mt = 0; mt < 2; mt++) {
            int row = wm * 32 + mt * 16 + g;
#pragma unroll
            for (int nt = 0; nt < 8; nt++) {
                int col = wn * 64 + nt * 8 + tig * 2;
                ps[row * 260 + col]           = sacc[mt][nt][0] * 0.125f;
                ps[row * 260 + col + 1]       = sacc[mt][nt][1] * 0.125f;
                ps[(row + 8) * 260 + col]     = sacc[mt][nt][2] * 0.125f;
                ps[(row + 8) * 260 + col + 1] = sacc[mt][nt][3] * 0.125f;
            }
        }
    }
    __syncthreads();

    // ---- softmax over 256 per row (fp32); store probs tf32-rounded ----
    {
        const int warp = wid;
        for (int rr = 0; rr < 8; rr++) {
            int r = warp * 8 + rr;
            float v[8], mx = -1e30f;
#pragma unroll
            for (int j = 0; j < 8; j++) {
                v[j] = ps[r * 260 + lane + j * 32];
                mx = fmaxf(mx, v[j]);
            }
#pragma unroll
            for (int s = 16; s > 0; s >>= 1)
                mx = fmaxf(mx, __shfl_xor_sync(0xffffffffu, mx, s));
            float sum = 0.f;
#pragma unroll
            for (int j = 0; j < 8; j++) { v[j] = __expf(v[j] - mx); sum += v[j]; }
#pragma unroll
            for (int s = 16; s > 0; s >>= 1)
                sum += __shfl_xor_sync(0xffffffffu, sum, s);
            float inv = 1.f / sum;
#pragma unroll
            for (int j = 0; j < 8; j++)
                ps[r * 260 + lane + j * 32] = tf32r(v[j] * inv);
        }
    }
    __syncthreads();

    // ---- O = P·V : warp tile 32(m) x 16(n), K=256 ----
    {
        float oacc[2][2][4];
#pragma unroll
        for (int mt = 0; mt < 2; mt++)
#pragma unroll
            for (int nt = 0; nt < 2; nt++)
#pragma unroll
                for (int r = 0; r < 4; r++) oacc[mt][nt][r] = 0.f;

        const uint32_t* psu = (const uint32_t*)ps;
        const uint32_t* vsu = (const uint32_t*)vs;
#pragma unroll 4
        for (int kk = 0; kk < 32; kk++) {
            int k = kk * 8;
            uint32_t af[2][4], bf[2][2];
#pragma unroll
            for (int mt = 0; mt < 2; mt++) {
                int row = wm * 32 + mt * 16 + g;
                af[mt][0] = psu[row * 260 + k + tig];
                af[mt][1] = psu[(row + 8) * 260 + k + tig];
                af[mt][2] = psu[row * 260 + k + tig + 4];
                af[mt][3] = psu[(row + 8) * 260 + k + tig + 4];
            }
#pragma unroll
            for (int nt = 0; nt < 2; nt++) {
                int n = wn * 16 + nt * 8 + g;
                bf[nt][0] = vsu[(k + tig) * 72 + n];
                bf[nt][1] = vsu[(k + tig + 4) * 72 + n];
            }
#pragma unroll
            for (int mt = 0; mt < 2; mt++)
#pragma unroll
                for (int nt = 0; nt < 2; nt++)
                    mma_tf32(oacc[mt][nt][0], oacc[mt][nt][1], oacc[mt][nt][2], oacc[mt][nt][3],
                             af[mt][0], af[mt][1], af[mt][2], af[mt][3],
                             bf[nt][0], bf[nt][1]);
        }
        // write O (tf32-rounded; feeds the O-projection GEMM)
#pragma unroll
        for (int mt = 0; mt < 2; mt++) {
            int row = wm * 32 + mt * 16 + g;
#pragma unroll
            for (int nt = 0; nt < 2; nt++) {
                int col = wn * 16 + nt * 8 + tig * 2;
                *(float2*)(O + qbase + (long long)row * DIMN + col) =
                    make_float2(tf32r(oacc[mt][nt][0]), tf32r(oacc[mt][nt][1]));
                *(float2*)(O + qbase + (long long)(row + 8) * DIMN + col) =
                    make_float2(tf32r(oacc[mt][nt][2]), tf32r(oacc[mt][nt][3]));
            }
        }
    }
}

// =====================================================================
// launch
// =====================================================================
extern "C" void kernel_launch(void* const* d_in, const int* in_sizes, int n_in,
                              void* d_out, int out_size)
{
    (void)in_sizes; (void)n_in; (void)out_size;

    const float* x  = (const float*)d_in[0];
    const float* Wq = (const float*)d_in[1];
    const float* Wk = (const float*)d_in[2];
    const float* Wv = (const float*)d_in[3];
    const float* pk = (const float*)d_in[4];
    const float* pv = (const float*)d_in[5];
    const float* Wo = (const float*)d_in[6];
    const float* bo = (const float*)d_in[7];
    float* out = (float*)d_out;

    float *Q, *AO, *keys, *vals, *xk, *xv;
    float *xt, *wqt, *wkt, *wvt, *wot, *pkt, *pvt;
    cudaGetSymbolAddress((void**)&Q, g_Q);
    cudaGetSymbolAddress((void**)&AO, g_AO);
    cudaGetSymbolAddress((void**)&keys, g_keys);
    cudaGetSymbolAddress((void**)&vals, g_vals);
    cudaGetSymbolAddress((void**)&xk, g_xk);
    cudaGetSymbolAddress((void**)&xv, g_xv);
    cudaGetSymbolAddress((void**)&xt, g_xt);
    cudaGetSymbolAddress((void**)&wqt, g_wqt);
    cudaGetSymbolAddress((void**)&wkt, g_wkt);
    cudaGetSymbolAddress((void**)&wvt, g_wvt);
    cudaGetSymbolAddress((void**)&wot, g_wot);
    cudaGetSymbolAddress((void**)&pkt, g_pkt);
    cudaGetSymbolAddress((void**)&pvt, g_pvt);

    // 0) round inputs to tf32 once
    {
        int n4x = (M_TOK * DIMN) / 4;
        round_tf32_kernel<<<(n4x + 255) / 256, 256>>>(x, xt, n4x);
        int n4w = (DIMN * DIMN) / 4;
        round_tf32_kernel<<<(n4w + 255) / 256, 256>>>(Wq, wqt, n4w);
        round_tf32_kernel<<<(n4w + 255) / 256, 256>>>(Wk, wkt, n4w);
        round_tf32_kernel<<<(n4w + 255) / 256, 256>>>(Wv, wvt, n4w);
        round_tf32_kernel<<<(n4w + 255) / 256, 256>>>(Wo, wot, n4w);
        int n4p = (SEQN * KLR) / 4;
        round_tf32_kernel<<<(n4p + 255) / 256, 256>>>(pk, pkt, n4p);
        round_tf32_kernel<<<(n4p + 255) / 256, 256>>>(pv, pvt, n4p);
    }

    // 1) Q projection — output tf32-rounded (feeds attention mma)
    dim3 gbig(DIMN / 128, M_TOK / 128);
    gemm_nt_tf32<<<gbig, 256>>>(xt, wqt, nullptr, Q, DIMN, DIMN, DIMN, DIMN, 0, 1);

    // 2) sequence projection of x first: xk = pk^T x, xv = pv^T x (rounded)
    dim3 gproj(DIMN / 128, KLR / 64, BATCHN);
    gemm_tn_tf32<<<gproj, 256>>>(pkt, xt, xk, SEQN, KLR, DIMN, DIMN,
                                 (long long)SEQN * DIMN, (long long)KLR * DIMN, 1);
    gemm_tn_tf32<<<gproj, 256>>>(pvt, xt, xv, SEQN, KLR, DIMN, DIMN,
                                 (long long)SEQN * DIMN, (long long)KLR * DIMN, 1);

    // 3) keys = xk·Wk^T, vals = xv·Wv^T — outputs tf32-rounded (feed attention)
    dim3 gsmall(DIMN / 128, (BATCHN * KLR) / 128);
    gemm_nt_tf32<<<gsmall, 256>>>(xk, wkt, nullptr, keys, DIMN, DIMN, DIMN, DIMN, 0, 1);
    gemm_nt_tf32<<<gsmall, 256>>>(xv, wvt, nullptr, vals, DIMN, DIMN, DIMN, DIMN, 0, 1);

    // 4) fused attention (tensor-core S and PV; writes tf32-rounded AO)
    cudaFuncSetAttribute(attn_kernel,
                         cudaFuncAttributeMaxDynamicSharedMemorySize,
                         ATT_SMEM_BYTES);
    dim3 gatt(SEQN / 64, HEADSN, BATCHN);
    attn_kernel<<<gatt, 256, ATT_SMEM_BYTES>>>(Q, keys, vals, AO);

    // 5) output projection + bias
    gemm_nt_tf32<<<gbig, 256>>>(AO, wot, bo, out, DIMN, DIMN, DIMN, DIMN, 1, 0);
}